// round 1
// baseline (speedup 1.0000x reference)
#include <cuda_runtime.h>

#define B 8
#define N 1024
#define FIN 256
#define FOUT 256
#define H 4
#define D 64
#define BN (B*N)

// Scratch (static __device__ — no allocation allowed)
__device__ float g_h [BN*FOUT];   // 32 MB: normalized features
__device__ float g_ei[BN*H];
__device__ float g_ej[BN*H];

// ---------------------------------------------------------------------------
// Kernel 1: h = x @ W   (M=8192, K=256, N=256), fp32, 32x256 block tile,
// 256 threads, 4x8 register tile per thread.
// ---------------------------------------------------------------------------
__global__ __launch_bounds__(256) void gemm_kernel(const float* __restrict__ x,
                                                   const float* __restrict__ W) {
    __shared__ float xs[32*32];    // 32 rows x 32 k
    __shared__ float ws[32*256];   // 32 k x 256 cols

    const int tid  = threadIdx.x;
    const int row0 = blockIdx.x * 32;
    const int mg   = tid >> 5;   // 0..7  (row group of 4)
    const int ng   = tid & 31;   // 0..31 (col group: cols ng*4..+3 and 128+ng*4..+3)

    float acc[4][8];
    #pragma unroll
    for (int i = 0; i < 4; i++)
        #pragma unroll
        for (int j = 0; j < 8; j++) acc[i][j] = 0.f;

    for (int kk = 0; kk < FIN; kk += 32) {
        // load x tile (32x32)
        {
            int idx = tid * 4;
            int r = idx >> 5, k = idx & 31;
            *(float4*)(xs + idx) = *(const float4*)(x + (size_t)(row0 + r) * FIN + kk + k);
        }
        // load W tile (32x256)
        #pragma unroll
        for (int i = 0; i < 8; i++) {
            int word = tid * 4 + i * 1024;
            int k = word >> 8, c = word & 255;
            *(float4*)(ws + word) = *(const float4*)(W + (size_t)(kk + k) * FOUT + c);
        }
        __syncthreads();

        #pragma unroll
        for (int k = 0; k < 32; k++) {
            float a0 = xs[(mg*4 + 0)*32 + k];
            float a1 = xs[(mg*4 + 1)*32 + k];
            float a2 = xs[(mg*4 + 2)*32 + k];
            float a3 = xs[(mg*4 + 3)*32 + k];
            float4 b0 = *(const float4*)(ws + k*256 + ng*4);        // conflict-free
            float4 b1 = *(const float4*)(ws + k*256 + 128 + ng*4);  // conflict-free
            acc[0][0] += a0*b0.x; acc[0][1] += a0*b0.y; acc[0][2] += a0*b0.z; acc[0][3] += a0*b0.w;
            acc[0][4] += a0*b1.x; acc[0][5] += a0*b1.y; acc[0][6] += a0*b1.z; acc[0][7] += a0*b1.w;
            acc[1][0] += a1*b0.x; acc[1][1] += a1*b0.y; acc[1][2] += a1*b0.z; acc[1][3] += a1*b0.w;
            acc[1][4] += a1*b1.x; acc[1][5] += a1*b1.y; acc[1][6] += a1*b1.z; acc[1][7] += a1*b1.w;
            acc[2][0] += a2*b0.x; acc[2][1] += a2*b0.y; acc[2][2] += a2*b0.z; acc[2][3] += a2*b0.w;
            acc[2][4] += a2*b1.x; acc[2][5] += a2*b1.y; acc[2][6] += a2*b1.z; acc[2][7] += a2*b1.w;
            acc[3][0] += a3*b0.x; acc[3][1] += a3*b0.y; acc[3][2] += a3*b0.z; acc[3][3] += a3*b0.w;
            acc[3][4] += a3*b1.x; acc[3][5] += a3*b1.y; acc[3][6] += a3*b1.z; acc[3][7] += a3*b1.w;
        }
        __syncthreads();
    }

    #pragma unroll
    for (int mi = 0; mi < 4; mi++) {
        int row = row0 + mg*4 + mi;
        float4 o0 = make_float4(acc[mi][0], acc[mi][1], acc[mi][2], acc[mi][3]);
        float4 o1 = make_float4(acc[mi][4], acc[mi][5], acc[mi][6], acc[mi][7]);
        *(float4*)(g_h + (size_t)row * FOUT + ng*4)       = o0;
        *(float4*)(g_h + (size_t)row * FOUT + 128 + ng*4) = o1;
    }
}

// ---------------------------------------------------------------------------
// Kernel 2: LayerNorm (in place on g_h) + per-head logits e_i, e_j.
// One block per row (256 threads, one per feature).
// ---------------------------------------------------------------------------
__global__ __launch_bounds__(256) void ln_kernel(const float* __restrict__ gamma,
                                                 const float* __restrict__ beta,
                                                 const float* __restrict__ a) {
    const int row = blockIdx.x;
    const int t   = threadIdx.x;
    const int warp = t >> 5, lane = t & 31;

    float v = g_h[(size_t)row * FOUT + t];

    __shared__ float red1[8], red2[8], rs[8], rd[8];

    // mean
    float s = v;
    #pragma unroll
    for (int o = 16; o; o >>= 1) s += __shfl_xor_sync(0xffffffffu, s, o);
    if (lane == 0) red1[warp] = s;
    __syncthreads();
    float mu = 0.f;
    #pragma unroll
    for (int i = 0; i < 8; i++) mu += red1[i];
    mu *= (1.0f / FOUT);

    // variance (two-pass)
    float dv = v - mu;
    float q = dv * dv;
    #pragma unroll
    for (int o = 16; o; o >>= 1) q += __shfl_xor_sync(0xffffffffu, q, o);
    if (lane == 0) red2[warp] = q;
    __syncthreads();
    float var = 0.f;
    #pragma unroll
    for (int i = 0; i < 8; i++) var += red2[i];
    var *= (1.0f / FOUT);

    float hn = dv * rsqrtf(var + 1e-5f) * gamma[t] + beta[t];
    g_h[(size_t)row * FOUT + t] = hn;

    // per-head dot with a_src / a_dst. Head = t/64 → each warp entirely in one head.
    const int d = t & 63;
    float ps = hn * a[d];
    float pd = hn * a[D + d];
    #pragma unroll
    for (int o = 16; o; o >>= 1) {
        ps += __shfl_xor_sync(0xffffffffu, ps, o);
        pd += __shfl_xor_sync(0xffffffffu, pd, o);
    }
    if (lane == 0) { rs[warp] = ps; rd[warp] = pd; }
    __syncthreads();
    if (t < H) {
        g_ei[row*H + t] = rs[2*t] + rs[2*t + 1];
        g_ej[row*H + t] = rd[2*t] + rd[2*t + 1];
    }
}

// ---------------------------------------------------------------------------
// Kernel 3: sparse masked-softmax attention aggregation.
// One block per (b,i) row. Deterministic neighbor compaction via prefix scan.
// ---------------------------------------------------------------------------
__global__ __launch_bounds__(256) void agg_kernel(const float* __restrict__ adj,
                                                  float* __restrict__ out) {
    __shared__ unsigned short list[N];    // neighbor indices (ascending j)
    __shared__ float4 wgt[N];             // exp weights per neighbor (4 heads)
    __shared__ int    warpTot[8];
    __shared__ float  redm[8*4], redsum[8*4];
    __shared__ float  Mh[4], Sh[4];

    const int row = blockIdx.x;
    const int b   = row >> 10;
    const int t   = threadIdx.x;
    const int warp = t >> 5, lane = t & 31;

    // ---- Phase 1: deterministic compaction of adjacency row ----
    const float* arow = adj + (size_t)row * N;
    float4 av = *(const float4*)(arow + t*4);
    int c = 0;
    unsigned short loc[4];
    if (av.x != 0.f) loc[c++] = (unsigned short)(t*4 + 0);
    if (av.y != 0.f) loc[c++] = (unsigned short)(t*4 + 1);
    if (av.z != 0.f) loc[c++] = (unsigned short)(t*4 + 2);
    if (av.w != 0.f) loc[c++] = (unsigned short)(t*4 + 3);
    // warp inclusive scan of c
    int incl = c;
    #pragma unroll
    for (int o = 1; o < 32; o <<= 1) {
        int n = __shfl_up_sync(0xffffffffu, incl, o);
        if (lane >= o) incl += n;
    }
    if (lane == 31) warpTot[warp] = incl;
    __syncthreads();
    int wbase = 0;
    #pragma unroll
    for (int w = 0; w < 8; w++) if (w < warp) wbase += warpTot[w];
    int pos = wbase + incl - c;
    for (int q = 0; q < c; q++) list[pos + q] = loc[q];
    int deg = 0;
    #pragma unroll
    for (int w = 0; w < 8; w++) deg += warpTot[w];
    __syncthreads();

    const float4 ei = *(const float4*)(g_ei + row*H);

    // ---- Phase 2: per-head max over neighbors ----
    float m0 = -1e30f, m1 = -1e30f, m2 = -1e30f, m3 = -1e30f;
    for (int idx = t; idx < deg; idx += 256) {
        int j = list[idx];
        float4 ej = *(const float4*)(g_ej + (b*N + j)*H);
        float v0 = ei.x + ej.x; v0 = v0 > 0.f ? v0 : 0.2f*v0;
        float v1 = ei.y + ej.y; v1 = v1 > 0.f ? v1 : 0.2f*v1;
        float v2 = ei.z + ej.z; v2 = v2 > 0.f ? v2 : 0.2f*v2;
        float v3 = ei.w + ej.w; v3 = v3 > 0.f ? v3 : 0.2f*v3;
        m0 = fmaxf(m0, v0); m1 = fmaxf(m1, v1);
        m2 = fmaxf(m2, v2); m3 = fmaxf(m3, v3);
    }
    #pragma unroll
    for (int o = 16; o; o >>= 1) {
        m0 = fmaxf(m0, __shfl_xor_sync(0xffffffffu, m0, o));
        m1 = fmaxf(m1, __shfl_xor_sync(0xffffffffu, m1, o));
        m2 = fmaxf(m2, __shfl_xor_sync(0xffffffffu, m2, o));
        m3 = fmaxf(m3, __shfl_xor_sync(0xffffffffu, m3, o));
    }
    if (lane == 0) {
        redm[warp*4+0] = m0; redm[warp*4+1] = m1;
        redm[warp*4+2] = m2; redm[warp*4+3] = m3;
    }
    __syncthreads();
    if (t < 4) {
        float mm = -1e30f;
        #pragma unroll
        for (int w = 0; w < 8; w++) mm = fmaxf(mm, redm[w*4 + t]);
        Mh[t] = mm;
    }
    __syncthreads();
    const float M0 = Mh[0], M1 = Mh[1], M2 = Mh[2], M3 = Mh[3];

    // ---- Phase 3: exp weights + denominators ----
    float s0 = 0.f, s1 = 0.f, s2 = 0.f, s3 = 0.f;
    for (int idx = t; idx < deg; idx += 256) {
        int j = list[idx];
        float4 ej = *(const float4*)(g_ej + (b*N + j)*H);
        float v0 = ei.x + ej.x; v0 = v0 > 0.f ? v0 : 0.2f*v0;
        float v1 = ei.y + ej.y; v1 = v1 > 0.f ? v1 : 0.2f*v1;
        float v2 = ei.z + ej.z; v2 = v2 > 0.f ? v2 : 0.2f*v2;
        float v3 = ei.w + ej.w; v3 = v3 > 0.f ? v3 : 0.2f*v3;
        float w0 = __expf(v0 - M0), w1 = __expf(v1 - M1);
        float w2 = __expf(v2 - M2), w3 = __expf(v3 - M3);
        wgt[idx] = make_float4(w0, w1, w2, w3);
        s0 += w0; s1 += w1; s2 += w2; s3 += w3;
    }
    #pragma unroll
    for (int o = 16; o; o >>= 1) {
        s0 += __shfl_xor_sync(0xffffffffu, s0, o);
        s1 += __shfl_xor_sync(0xffffffffu, s1, o);
        s2 += __shfl_xor_sync(0xffffffffu, s2, o);
        s3 += __shfl_xor_sync(0xffffffffu, s3, o);
    }
    if (lane == 0) {
        redsum[warp*4+0] = s0; redsum[warp*4+1] = s1;
        redsum[warp*4+2] = s2; redsum[warp*4+3] = s3;
    }
    __syncthreads();
    if (t < 4) {
        float ss = 0.f;
        #pragma unroll
        for (int w = 0; w < 8; w++) ss += redsum[w*4 + t];
        Sh[t] = ss;
    }
    __syncthreads();

    // ---- Phase 4: weighted gather of h rows ----
    const int hh = t >> 6;
    const float inv = 1.0f / Sh[hh];
    const float* wf = (const float*)wgt;
    float acc = 0.f;
    #pragma unroll 4
    for (int idx = 0; idx < deg; idx++) {
        int j = list[idx];
        float w = wf[idx*4 + hh];
        acc += w * g_h[(size_t)(b*N + j) * FOUT + t];
    }
    out[(size_t)row * FOUT + t] = acc * inv;
}

// ---------------------------------------------------------------------------
extern "C" void kernel_launch(void* const* d_in, const int* in_sizes, int n_in,
                              void* d_out, int out_size) {
    const float* x     = (const float*)d_in[0];
    const float* adj   = (const float*)d_in[1];
    const float* W     = (const float*)d_in[2];
    const float* gamma = (const float*)d_in[3];
    const float* beta  = (const float*)d_in[4];
    const float* a     = (const float*)d_in[5];
    float* out = (float*)d_out;

    gemm_kernel<<<BN/32, 256>>>(x, W);
    ln_kernel  <<<BN,    256>>>(gamma, beta, a);
    agg_kernel <<<BN,    256>>>(adj, out);
}

// round 2
// speedup vs baseline: 1.0497x; 1.0497x over previous
#include <cuda_runtime.h>
#include <cuda_fp16.h>

#define B 8
#define N 1024
#define FIN 256
#define FOUT 256
#define H 4
#define D 64
#define BN (B*N)

// Scratch (static __device__ — no allocation allowed)
__device__ float  g_h [BN*FOUT];   // fp32 normalized features (exactness anchor)
__device__ __half g_hh[BN*FOUT];   // fp16 mirror for the aggregation gather
__device__ float  g_ei[BN*H];
__device__ float  g_ej[BN*H];

// ---------------------------------------------------------------------------
// Kernel 1: h = x @ W  (8192x256x256 fp32) with FUSED LayerNorm + head logits.
// Block tile 32x256, 256 threads, 4x8 register tile. Each warp owns 4 full
// rows -> LN + e_i/e_j are pure warp-shuffle reductions.
// ---------------------------------------------------------------------------
__global__ __launch_bounds__(256) void gemm_ln_kernel(const float* __restrict__ x,
                                                      const float* __restrict__ W,
                                                      const float* __restrict__ gamma,
                                                      const float* __restrict__ beta,
                                                      const float* __restrict__ a) {
    __shared__ float xs[32*32];    // 32 rows x 32 k
    __shared__ float ws[32*256];   // 32 k x 256 cols

    const int tid  = threadIdx.x;
    const int row0 = blockIdx.x * 32;
    const int mg   = tid >> 5;   // warp id = row group of 4
    const int ng   = tid & 31;   // lane: cols ng*4..+3 and 128+ng*4..+3

    float acc[4][8];
    #pragma unroll
    for (int i = 0; i < 4; i++)
        #pragma unroll
        for (int j = 0; j < 8; j++) acc[i][j] = 0.f;

    for (int kk = 0; kk < FIN; kk += 32) {
        {
            int idx = tid * 4;
            int r = idx >> 5, k = idx & 31;
            *(float4*)(xs + idx) = *(const float4*)(x + (size_t)(row0 + r) * FIN + kk + k);
        }
        #pragma unroll
        for (int i = 0; i < 8; i++) {
            int word = tid * 4 + i * 1024;
            int k = word >> 8, c = word & 255;
            *(float4*)(ws + word) = *(const float4*)(W + (size_t)(kk + k) * FOUT + c);
        }
        __syncthreads();

        #pragma unroll
        for (int k = 0; k < 32; k++) {
            float a0 = xs[(mg*4 + 0)*32 + k];
            float a1 = xs[(mg*4 + 1)*32 + k];
            float a2 = xs[(mg*4 + 2)*32 + k];
            float a3 = xs[(mg*4 + 3)*32 + k];
            float4 b0 = *(const float4*)(ws + k*256 + ng*4);
            float4 b1 = *(const float4*)(ws + k*256 + 128 + ng*4);
            acc[0][0] += a0*b0.x; acc[0][1] += a0*b0.y; acc[0][2] += a0*b0.z; acc[0][3] += a0*b0.w;
            acc[0][4] += a0*b1.x; acc[0][5] += a0*b1.y; acc[0][6] += a0*b1.z; acc[0][7] += a0*b1.w;
            acc[1][0] += a1*b0.x; acc[1][1] += a1*b0.y; acc[1][2] += a1*b0.z; acc[1][3] += a1*b0.w;
            acc[1][4] += a1*b1.x; acc[1][5] += a1*b1.y; acc[1][6] += a1*b1.z; acc[1][7] += a1*b1.w;
            acc[2][0] += a2*b0.x; acc[2][1] += a2*b0.y; acc[2][2] += a2*b0.z; acc[2][3] += a2*b0.w;
            acc[2][4] += a2*b1.x; acc[2][5] += a2*b1.y; acc[2][6] += a2*b1.z; acc[2][7] += a2*b1.w;
            acc[3][0] += a3*b0.x; acc[3][1] += a3*b0.y; acc[3][2] += a3*b0.z; acc[3][3] += a3*b0.w;
            acc[3][4] += a3*b1.x; acc[3][5] += a3*b1.y; acc[3][6] += a3*b1.z; acc[3][7] += a3*b1.w;
        }
        __syncthreads();
    }

    // ---- Fused epilogue: LayerNorm + h stores + e_i/e_j head dots ----
    // Column indexing: j<4 -> c = ng*4+j (heads 0/1), j>=4 -> c = 128+ng*4+(j-4)
    // (heads 2/3). d = c & 63 is identical for the lo/hi groups.
    const int d0 = (ng * 4) & 63;
    const float4 asv = *(const float4*)(a + d0);        // a_src[d0..d0+3]
    const float4 adv = *(const float4*)(a + 64 + d0);   // a_dst[d0..d0+3]
    const float4 gv0 = *(const float4*)(gamma + ng*4);
    const float4 gv1 = *(const float4*)(gamma + 128 + ng*4);
    const float4 bv0 = *(const float4*)(beta  + ng*4);
    const float4 bv1 = *(const float4*)(beta  + 128 + ng*4);

    #pragma unroll
    for (int mi = 0; mi < 4; mi++) {
        const int row = row0 + mg*4 + mi;

        float s = 0.f;
        #pragma unroll
        for (int j = 0; j < 8; j++) s += acc[mi][j];
        #pragma unroll
        for (int o = 16; o; o >>= 1) s += __shfl_xor_sync(0xffffffffu, s, o);
        const float mu = s * (1.0f / FOUT);

        float q = 0.f;
        #pragma unroll
        for (int j = 0; j < 8; j++) { float dv = acc[mi][j] - mu; q += dv * dv; }
        #pragma unroll
        for (int o = 16; o; o >>= 1) q += __shfl_xor_sync(0xffffffffu, q, o);
        const float rstd = rsqrtf(q * (1.0f / FOUT) + 1e-5f);

        float hn[8];
        hn[0] = (acc[mi][0]-mu)*rstd*gv0.x + bv0.x;
        hn[1] = (acc[mi][1]-mu)*rstd*gv0.y + bv0.y;
        hn[2] = (acc[mi][2]-mu)*rstd*gv0.z + bv0.z;
        hn[3] = (acc[mi][3]-mu)*rstd*gv0.w + bv0.w;
        hn[4] = (acc[mi][4]-mu)*rstd*gv1.x + bv1.x;
        hn[5] = (acc[mi][5]-mu)*rstd*gv1.y + bv1.y;
        hn[6] = (acc[mi][6]-mu)*rstd*gv1.z + bv1.z;
        hn[7] = (acc[mi][7]-mu)*rstd*gv1.w + bv1.w;

        // fp32 store
        *(float4*)(g_h + (size_t)row * FOUT + ng*4)       = make_float4(hn[0],hn[1],hn[2],hn[3]);
        *(float4*)(g_h + (size_t)row * FOUT + 128 + ng*4) = make_float4(hn[4],hn[5],hn[6],hn[7]);
        // fp16 mirror
        *(__half2*)(g_hh + (size_t)row * FOUT + ng*4)           = __floats2half2_rn(hn[0], hn[1]);
        *(__half2*)(g_hh + (size_t)row * FOUT + ng*4 + 2)       = __floats2half2_rn(hn[2], hn[3]);
        *(__half2*)(g_hh + (size_t)row * FOUT + 128 + ng*4)     = __floats2half2_rn(hn[4], hn[5]);
        *(__half2*)(g_hh + (size_t)row * FOUT + 128 + ng*4 + 2) = __floats2half2_rn(hn[6], hn[7]);

        // head-dot partials: lanes 0..15 -> heads (0,2), lanes 16..31 -> heads (1,3)
        float psl = hn[0]*asv.x + hn[1]*asv.y + hn[2]*asv.z + hn[3]*asv.w;
        float psh = hn[4]*asv.x + hn[5]*asv.y + hn[6]*asv.z + hn[7]*asv.w;
        float pdl = hn[0]*adv.x + hn[1]*adv.y + hn[2]*adv.z + hn[3]*adv.w;
        float pdh = hn[4]*adv.x + hn[5]*adv.y + hn[6]*adv.z + hn[7]*adv.w;
        #pragma unroll
        for (int o = 8; o; o >>= 1) {   // reduce within 16-lane half
            psl += __shfl_xor_sync(0xffffffffu, psl, o);
            psh += __shfl_xor_sync(0xffffffffu, psh, o);
            pdl += __shfl_xor_sync(0xffffffffu, pdl, o);
            pdh += __shfl_xor_sync(0xffffffffu, pdh, o);
        }
        if (ng == 0) {          // heads 0 and 2
            g_ei[row*H + 0] = psl; g_ei[row*H + 2] = psh;
            g_ej[row*H + 0] = pdl; g_ej[row*H + 2] = pdh;
        } else if (ng == 16) {  // heads 1 and 3
            g_ei[row*H + 1] = psl; g_ei[row*H + 3] = psh;
            g_ej[row*H + 1] = pdl; g_ej[row*H + 3] = pdh;
        }
    }
}

// ---------------------------------------------------------------------------
// Kernel 2: sparse masked-softmax attention aggregation.
// One block per (b,i) row. Deterministic neighbor compaction via prefix scan.
// Phase-4 gather reads the fp16 mirror (half the L2 traffic).
// ---------------------------------------------------------------------------
__global__ __launch_bounds__(256) void agg_kernel(const float* __restrict__ adj,
                                                  float* __restrict__ out) {
    __shared__ unsigned short list[N];    // neighbor indices (ascending j)
    __shared__ float4 wgt[N];             // exp weights per neighbor (4 heads)
    __shared__ int    warpTot[8];
    __shared__ float  redm[8*4], redsum[8*4];
    __shared__ float  Mh[4], Sh[4];

    const int row = blockIdx.x;
    const int b   = row >> 10;
    const int t   = threadIdx.x;
    const int warp = t >> 5, lane = t & 31;

    // ---- Phase 1: deterministic compaction of adjacency row ----
    const float* arow = adj + (size_t)row * N;
    float4 av = *(const float4*)(arow + t*4);
    int c = 0;
    unsigned short loc[4];
    if (av.x != 0.f) loc[c++] = (unsigned short)(t*4 + 0);
    if (av.y != 0.f) loc[c++] = (unsigned short)(t*4 + 1);
    if (av.z != 0.f) loc[c++] = (unsigned short)(t*4 + 2);
    if (av.w != 0.f) loc[c++] = (unsigned short)(t*4 + 3);
    int incl = c;
    #pragma unroll
    for (int o = 1; o < 32; o <<= 1) {
        int n = __shfl_up_sync(0xffffffffu, incl, o);
        if (lane >= o) incl += n;
    }
    if (lane == 31) warpTot[warp] = incl;
    __syncthreads();
    int wbase = 0;
    #pragma unroll
    for (int w = 0; w < 8; w++) if (w < warp) wbase += warpTot[w];
    int pos = wbase + incl - c;
    for (int q = 0; q < c; q++) list[pos + q] = loc[q];
    int deg = 0;
    #pragma unroll
    for (int w = 0; w < 8; w++) deg += warpTot[w];
    __syncthreads();

    const float4 ei = *(const float4*)(g_ei + row*H);

    // ---- Phase 2: per-head max over neighbors ----
    float m0 = -1e30f, m1 = -1e30f, m2 = -1e30f, m3 = -1e30f;
    for (int idx = t; idx < deg; idx += 256) {
        int j = list[idx];
        float4 ej = *(const float4*)(g_ej + (b*N + j)*H);
        float v0 = ei.x + ej.x; v0 = v0 > 0.f ? v0 : 0.2f*v0;
        float v1 = ei.y + ej.y; v1 = v1 > 0.f ? v1 : 0.2f*v1;
        float v2 = ei.z + ej.z; v2 = v2 > 0.f ? v2 : 0.2f*v2;
        float v3 = ei.w + ej.w; v3 = v3 > 0.f ? v3 : 0.2f*v3;
        m0 = fmaxf(m0, v0); m1 = fmaxf(m1, v1);
        m2 = fmaxf(m2, v2); m3 = fmaxf(m3, v3);
    }
    #pragma unroll
    for (int o = 16; o; o >>= 1) {
        m0 = fmaxf(m0, __shfl_xor_sync(0xffffffffu, m0, o));
        m1 = fmaxf(m1, __shfl_xor_sync(0xffffffffu, m1, o));
        m2 = fmaxf(m2, __shfl_xor_sync(0xffffffffu, m2, o));
        m3 = fmaxf(m3, __shfl_xor_sync(0xffffffffu, m3, o));
    }
    if (lane == 0) {
        redm[warp*4+0] = m0; redm[warp*4+1] = m1;
        redm[warp*4+2] = m2; redm[warp*4+3] = m3;
    }
    __syncthreads();
    if (t < 4) {
        float mm = -1e30f;
        #pragma unroll
        for (int w = 0; w < 8; w++) mm = fmaxf(mm, redm[w*4 + t]);
        Mh[t] = mm;
    }
    __syncthreads();
    const float M0 = Mh[0], M1 = Mh[1], M2 = Mh[2], M3 = Mh[3];

    // ---- Phase 3: exp weights + denominators ----
    float s0 = 0.f, s1 = 0.f, s2 = 0.f, s3 = 0.f;
    for (int idx = t; idx < deg; idx += 256) {
        int j = list[idx];
        float4 ej = *(const float4*)(g_ej + (b*N + j)*H);
        float v0 = ei.x + ej.x; v0 = v0 > 0.f ? v0 : 0.2f*v0;
        float v1 = ei.y + ej.y; v1 = v1 > 0.f ? v1 : 0.2f*v1;
        float v2 = ei.z + ej.z; v2 = v2 > 0.f ? v2 : 0.2f*v2;
        float v3 = ei.w + ej.w; v3 = v3 > 0.f ? v3 : 0.2f*v3;
        float w0 = __expf(v0 - M0), w1 = __expf(v1 - M1);
        float w2 = __expf(v2 - M2), w3 = __expf(v3 - M3);
        wgt[idx] = make_float4(w0, w1, w2, w3);
        s0 += w0; s1 += w1; s2 += w2; s3 += w3;
    }
    #pragma unroll
    for (int o = 16; o; o >>= 1) {
        s0 += __shfl_xor_sync(0xffffffffu, s0, o);
        s1 += __shfl_xor_sync(0xffffffffu, s1, o);
        s2 += __shfl_xor_sync(0xffffffffu, s2, o);
        s3 += __shfl_xor_sync(0xffffffffu, s3, o);
    }
    if (lane == 0) {
        redsum[warp*4+0] = s0; redsum[warp*4+1] = s1;
        redsum[warp*4+2] = s2; redsum[warp*4+3] = s3;
    }
    __syncthreads();
    if (t < 4) {
        float ss = 0.f;
        #pragma unroll
        for (int w = 0; w < 8; w++) ss += redsum[w*4 + t];
        Sh[t] = ss;
    }
    __syncthreads();

    // ---- Phase 4: weighted gather of h rows (fp16 mirror) ----
    const int hh = t >> 6;
    const float inv = 1.0f / Sh[hh];
    const float* wf = (const float*)wgt;
    float acc = 0.f;
    #pragma unroll 4
    for (int idx = 0; idx < deg; idx++) {
        int j = list[idx];
        float w = wf[idx*4 + hh];
        acc += w * __half2float(g_hh[(size_t)(b*N + j) * FOUT + t]);
    }
    out[(size_t)row * FOUT + t] = acc * inv;
}

// ---------------------------------------------------------------------------
extern "C" void kernel_launch(void* const* d_in, const int* in_sizes, int n_in,
                              void* d_out, int out_size) {
    const float* x     = (const float*)d_in[0];
    const float* adj   = (const float*)d_in[1];
    const float* W     = (const float*)d_in[2];
    const float* gamma = (const float*)d_in[3];
    const float* beta  = (const float*)d_in[4];
    const float* a     = (const float*)d_in[5];
    float* out = (float*)d_out;

    gemm_ln_kernel<<<BN/32, 256>>>(x, W, gamma, beta, a);
    agg_kernel    <<<BN,    256>>>(adj, out);
}

// round 5
// speedup vs baseline: 1.4832x; 1.4130x over previous
#include <cuda_runtime.h>
#include <cuda_fp16.h>

#define B 8
#define N 1024
#define FIN 256
#define FOUT 256
#define H 4
#define D 64
#define BN (B*N)

// Scratch (static __device__ — no allocation allowed)
__device__ float  g_h [BN*FOUT];   // fp32 normalized features
__device__ __half g_hh[BN*FOUT];   // fp16 mirror for the aggregation gather
__device__ float  g_ei[BN*H];
__device__ float  g_ej[BN*H];

// ---------------------------------------------------------------------------
// Kernel 1: h = x @ W  (8192x256x256 fp32) with FUSED LayerNorm + head logits.
// ---------------------------------------------------------------------------
__global__ __launch_bounds__(256) void gemm_ln_kernel(const float* __restrict__ x,
                                                      const float* __restrict__ W,
                                                      const float* __restrict__ gamma,
                                                      const float* __restrict__ beta,
                                                      const float* __restrict__ a) {
    __shared__ float xs[32*32];
    __shared__ float ws[32*256];

    const int tid  = threadIdx.x;
    const int row0 = blockIdx.x * 32;
    const int mg   = tid >> 5;
    const int ng   = tid & 31;

    float acc[4][8];
    #pragma unroll
    for (int i = 0; i < 4; i++)
        #pragma unroll
        for (int j = 0; j < 8; j++) acc[i][j] = 0.f;

    for (int kk = 0; kk < FIN; kk += 32) {
        {
            int idx = tid * 4;
            int r = idx >> 5, k = idx & 31;
            *(float4*)(xs + idx) = *(const float4*)(x + (size_t)(row0 + r) * FIN + kk + k);
        }
        #pragma unroll
        for (int i = 0; i < 8; i++) {
            int word = tid * 4 + i * 1024;
            int k = word >> 8, c = word & 255;
            *(float4*)(ws + word) = *(const float4*)(W + (size_t)(kk + k) * FOUT + c);
        }
        __syncthreads();

        #pragma unroll
        for (int k = 0; k < 32; k++) {
            float a0 = xs[(mg*4 + 0)*32 + k];
            float a1 = xs[(mg*4 + 1)*32 + k];
            float a2 = xs[(mg*4 + 2)*32 + k];
            float a3 = xs[(mg*4 + 3)*32 + k];
            float4 b0 = *(const float4*)(ws + k*256 + ng*4);
            float4 b1 = *(const float4*)(ws + k*256 + 128 + ng*4);
            acc[0][0] += a0*b0.x; acc[0][1] += a0*b0.y; acc[0][2] += a0*b0.z; acc[0][3] += a0*b0.w;
            acc[0][4] += a0*b1.x; acc[0][5] += a0*b1.y; acc[0][6] += a0*b1.z; acc[0][7] += a0*b1.w;
            acc[1][0] += a1*b0.x; acc[1][1] += a1*b0.y; acc[1][2] += a1*b0.z; acc[1][3] += a1*b0.w;
            acc[1][4] += a1*b1.x; acc[1][5] += a1*b1.y; acc[1][6] += a1*b1.z; acc[1][7] += a1*b1.w;
            acc[2][0] += a2*b0.x; acc[2][1] += a2*b0.y; acc[2][2] += a2*b0.z; acc[2][3] += a2*b0.w;
            acc[2][4] += a2*b1.x; acc[2][5] += a2*b1.y; acc[2][6] += a2*b1.z; acc[2][7] += a2*b1.w;
            acc[3][0] += a3*b0.x; acc[3][1] += a3*b0.y; acc[3][2] += a3*b0.z; acc[3][3] += a3*b0.w;
            acc[3][4] += a3*b1.x; acc[3][5] += a3*b1.y; acc[3][6] += a3*b1.z; acc[3][7] += a3*b1.w;
        }
        __syncthreads();
    }

    const int d0 = (ng * 4) & 63;
    const float4 asv = *(const float4*)(a + d0);
    const float4 adv = *(const float4*)(a + 64 + d0);
    const float4 gv0 = *(const float4*)(gamma + ng*4);
    const float4 gv1 = *(const float4*)(gamma + 128 + ng*4);
    const float4 bv0 = *(const float4*)(beta  + ng*4);
    const float4 bv1 = *(const float4*)(beta  + 128 + ng*4);

    #pragma unroll
    for (int mi = 0; mi < 4; mi++) {
        const int row = row0 + mg*4 + mi;

        float s = 0.f;
        #pragma unroll
        for (int j = 0; j < 8; j++) s += acc[mi][j];
        #pragma unroll
        for (int o = 16; o; o >>= 1) s += __shfl_xor_sync(0xffffffffu, s, o);
        const float mu = s * (1.0f / FOUT);

        float q = 0.f;
        #pragma unroll
        for (int j = 0; j < 8; j++) { float dv = acc[mi][j] - mu; q += dv * dv; }
        #pragma unroll
        for (int o = 16; o; o >>= 1) q += __shfl_xor_sync(0xffffffffu, q, o);
        const float rstd = rsqrtf(q * (1.0f / FOUT) + 1e-5f);

        float hn[8];
        hn[0] = (acc[mi][0]-mu)*rstd*gv0.x + bv0.x;
        hn[1] = (acc[mi][1]-mu)*rstd*gv0.y + bv0.y;
        hn[2] = (acc[mi][2]-mu)*rstd*gv0.z + bv0.z;
        hn[3] = (acc[mi][3]-mu)*rstd*gv0.w + bv0.w;
        hn[4] = (acc[mi][4]-mu)*rstd*gv1.x + bv1.x;
        hn[5] = (acc[mi][5]-mu)*rstd*gv1.y + bv1.y;
        hn[6] = (acc[mi][6]-mu)*rstd*gv1.z + bv1.z;
        hn[7] = (acc[mi][7]-mu)*rstd*gv1.w + bv1.w;

        *(float4*)(g_h + (size_t)row * FOUT + ng*4)       = make_float4(hn[0],hn[1],hn[2],hn[3]);
        *(float4*)(g_h + (size_t)row * FOUT + 128 + ng*4) = make_float4(hn[4],hn[5],hn[6],hn[7]);

        __half2* hp0 = (__half2*)(g_hh + (size_t)row * FOUT + ng*4);
        hp0[0] = __floats2half2_rn(hn[0], hn[1]);
        hp0[1] = __floats2half2_rn(hn[2], hn[3]);
        __half2* hp1 = (__half2*)(g_hh + (size_t)row * FOUT + 128 + ng*4);
        hp1[0] = __floats2half2_rn(hn[4], hn[5]);
        hp1[1] = __floats2half2_rn(hn[6], hn[7]);

        float psl = hn[0]*asv.x + hn[1]*asv.y + hn[2]*asv.z + hn[3]*asv.w;
        float psh = hn[4]*asv.x + hn[5]*asv.y + hn[6]*asv.z + hn[7]*asv.w;
        float pdl = hn[0]*adv.x + hn[1]*adv.y + hn[2]*adv.z + hn[3]*adv.w;
        float pdh = hn[4]*adv.x + hn[5]*adv.y + hn[6]*adv.z + hn[7]*adv.w;
        #pragma unroll
        for (int o = 8; o; o >>= 1) {
            psl += __shfl_xor_sync(0xffffffffu, psl, o);
            psh += __shfl_xor_sync(0xffffffffu, psh, o);
            pdl += __shfl_xor_sync(0xffffffffu, pdl, o);
            pdh += __shfl_xor_sync(0xffffffffu, pdh, o);
        }
        if (ng == 0) {
            g_ei[row*H + 0] = psl; g_ei[row*H + 2] = psh;
            g_ej[row*H + 0] = pdl; g_ej[row*H + 2] = pdh;
        } else if (ng == 16) {
            g_ei[row*H + 1] = psl; g_ei[row*H + 3] = psh;
            g_ej[row*H + 1] = pdl; g_ej[row*H + 3] = pdh;
        }
    }
}

// ---------------------------------------------------------------------------
// Kernel 2: sparse masked-softmax aggregation.
//  - no max pass (logits bounded; exp safe; softmax shift-invariant)
//  - gather vectorized: 4 neighbors in flight, each thread loads 4 halves
//    (LDG.64) with 32-bit addressing; SMEM reduction of 4 partials.
// ---------------------------------------------------------------------------
__global__ __launch_bounds__(256) void agg_kernel(const float* __restrict__ adj,
                                                  float* __restrict__ out) {
    __shared__ unsigned short list[N];
    __shared__ float4 wgt[N];           // exp weights per neighbor (4 heads)
    __shared__ int    warpTot[8];
    __shared__ float  redsum[8*4];
    __shared__ float  Sh[4];
    __shared__ float4 part[4][64];      // gather partials [slot][feature-group]

    const int row = blockIdx.x;
    const int b   = row >> 10;
    const int t   = threadIdx.x;
    const int warp = t >> 5, lane = t & 31;

    // ---- Phase 1: deterministic compaction of adjacency row ----
    const float* arow = adj + (size_t)row * N;
    float4 av = *(const float4*)(arow + t*4);
    int c = 0;
    unsigned short loc[4];
    if (av.x != 0.f) loc[c++] = (unsigned short)(t*4 + 0);
    if (av.y != 0.f) loc[c++] = (unsigned short)(t*4 + 1);
    if (av.z != 0.f) loc[c++] = (unsigned short)(t*4 + 2);
    if (av.w != 0.f) loc[c++] = (unsigned short)(t*4 + 3);
    int incl = c;
    #pragma unroll
    for (int o = 1; o < 32; o <<= 1) {
        int n = __shfl_up_sync(0xffffffffu, incl, o);
        if (lane >= o) incl += n;
    }
    if (lane == 31) warpTot[warp] = incl;
    __syncthreads();
    int wbase = 0;
    #pragma unroll
    for (int w = 0; w < 8; w++) if (w < warp) wbase += warpTot[w];
    int pos = wbase + incl - c;
    for (int q = 0; q < c; q++) list[pos + q] = loc[q];
    int deg = 0;
    #pragma unroll
    for (int w = 0; w < 8; w++) deg += warpTot[w];
    __syncthreads();

    const float4 ei = *(const float4*)(g_ei + row*H);

    // ---- Phase 2: exp weights + denominators (no max subtraction) ----
    const float* ejbase = g_ej + b*N*H;
    float s0 = 0.f, s1 = 0.f, s2 = 0.f, s3 = 0.f;
    for (int idx = t; idx < deg; idx += 256) {
        int j = list[idx];
        float4 ej = *(const float4*)(ejbase + j*H);
        float v0 = ei.x + ej.x; v0 = v0 > 0.f ? v0 : 0.2f*v0;
        float v1 = ei.y + ej.y; v1 = v1 > 0.f ? v1 : 0.2f*v1;
        float v2 = ei.z + ej.z; v2 = v2 > 0.f ? v2 : 0.2f*v2;
        float v3 = ei.w + ej.w; v3 = v3 > 0.f ? v3 : 0.2f*v3;
        float w0 = __expf(v0), w1 = __expf(v1);
        float w2 = __expf(v2), w3 = __expf(v3);
        wgt[idx] = make_float4(w0, w1, w2, w3);
        s0 += w0; s1 += w1; s2 += w2; s3 += w3;
    }
    #pragma unroll
    for (int o = 16; o; o >>= 1) {
        s0 += __shfl_xor_sync(0xffffffffu, s0, o);
        s1 += __shfl_xor_sync(0xffffffffu, s1, o);
        s2 += __shfl_xor_sync(0xffffffffu, s2, o);
        s3 += __shfl_xor_sync(0xffffffffu, s3, o);
    }
    if (lane == 0) {
        redsum[warp*4+0] = s0; redsum[warp*4+1] = s1;
        redsum[warp*4+2] = s2; redsum[warp*4+3] = s3;
    }
    __syncthreads();
    if (t < 4) {
        float ss = 0.f;
        #pragma unroll
        for (int w = 0; w < 8; w++) ss += redsum[w*4 + t];
        Sh[t] = ss;
    }
    __syncthreads();

    // ---- Phase 3: vectorized weighted gather ----
    // slot = t>>6 picks one of 4 concurrent neighbors; fg = t&63 picks the
    // 4-feature group [fg*4, fg*4+4). head = fg>>4.
    const int slot = t >> 6;
    const int fg   = t & 63;
    const int head = fg >> 4;
    const __half* hbase = g_hh + (size_t)b * (N*FOUT);
    const float*  wf    = (const float*)wgt;

    float a0 = 0.f, a1 = 0.f, a2 = 0.f, a3 = 0.f;
    for (int idx = slot; idx < deg; idx += 4) {
        int j = (int)list[idx];
        float w = wf[idx*4 + head];
        uint2 raw = *(const uint2*)(hbase + (j << 8) + fg*4);
        float2 u = __half22float2(*(const __half2*)&raw.x);
        float2 v = __half22float2(*(const __half2*)&raw.y);
        a0 += w*u.x; a1 += w*u.y; a2 += w*v.x; a3 += w*v.y;
    }
    part[slot][fg] = make_float4(a0, a1, a2, a3);
    __syncthreads();

    if (t < 64) {   // slot 0 threads finalize
        float4 r0 = part[0][t], r1 = part[1][t], r2 = part[2][t], r3 = part[3][t];
        const float inv = 1.0f / Sh[t >> 4];
        float4 o;
        o.x = (r0.x + r1.x + r2.x + r3.x) * inv;
        o.y = (r0.y + r1.y + r2.y + r3.y) * inv;
        o.z = (r0.z + r1.z + r2.z + r3.z) * inv;
        o.w = (r0.w + r1.w + r2.w + r3.w) * inv;
        *(float4*)(out + (size_t)row * FOUT + t*4) = o;
    }
}

// ---------------------------------------------------------------------------
extern "C" void kernel_launch(void* const* d_in, const int* in_sizes, int n_in,
                              void* d_out, int out_size) {
    const float* x     = (const float*)d_in[0];
    const float* adj   = (const float*)d_in[1];
    const float* W     = (const float*)d_in[2];
    const float* gamma = (const float*)d_in[3];
    const float* beta  = (const float*)d_in[4];
    const float* a     = (const float*)d_in[5];
    float* out = (float*)d_out;

    gemm_ln_kernel<<<BN/32, 256>>>(x, W, gamma, beta, a);
    agg_kernel    <<<BN,    256>>>(adj, out);
}

// round 7
// speedup vs baseline: 1.5662x; 1.0559x over previous
#include <cuda_runtime.h>
#include <cuda_fp16.h>

#define B 8
#define N 1024
#define FIN 256
#define FOUT 256
#define H 4
#define D 64
#define BN (B*N)

// Scratch (static __device__ — no allocation allowed)
__device__ __half g_hh[BN*FOUT];   // fp16 normalized features (gather source)
__device__ float  g_ei[BN*H];
__device__ float  g_ej[BN*H];

// packed f32x2 helpers (sm_103a FFMA2 — ptxas only emits via PTX f32x2)
#define PACK2(dst, s)     asm("mov.b64 %0,{%1,%1};" : "=l"(dst) : "f"(s))
#define FFMA2(acc, a, b)  asm("fma.rn.f32x2 %0,%1,%2,%0;" : "+l"(acc) : "l"(a), "l"(b))
#define UNPACK2(lo, hi, s) asm("mov.b64 {%0,%1},%2;" : "=f"(lo), "=f"(hi) : "l"(s))

// ---------------------------------------------------------------------------
// Kernel 1: h = x @ W  (8192x256x256 fp32, packed FFMA2) with FUSED
// LayerNorm + head logits. Block tile 32x256, 256 threads.
// ---------------------------------------------------------------------------
__global__ __launch_bounds__(256) void gemm_ln_kernel(const float* __restrict__ x,
                                                      const float* __restrict__ W,
                                                      const float* __restrict__ gamma,
                                                      const float* __restrict__ beta,
                                                      const float* __restrict__ a) {
    __shared__ float xs[32*32];
    __shared__ float ws[32*256];

    const int tid  = threadIdx.x;
    const int row0 = blockIdx.x * 32;
    const int mg   = tid >> 5;
    const int ng   = tid & 31;

    // acc2[mi][p]: packed pair (col 2p, col 2p+1) of the 8 columns this thread owns
    unsigned long long acc2[4][4];
    #pragma unroll
    for (int i = 0; i < 4; i++)
        #pragma unroll
        for (int j = 0; j < 4; j++) acc2[i][j] = 0ull;

    for (int kk = 0; kk < FIN; kk += 32) {
        {
            int idx = tid * 4;
            int r = idx >> 5, k = idx & 31;
            *(float4*)(xs + idx) = *(const float4*)(x + (size_t)(row0 + r) * FIN + kk + k);
        }
        #pragma unroll
        for (int i = 0; i < 8; i++) {
            int word = tid * 4 + i * 1024;
            int k = word >> 8, c = word & 255;
            *(float4*)(ws + word) = *(const float4*)(W + (size_t)(kk + k) * FOUT + c);
        }
        __syncthreads();

        #pragma unroll
        for (int k = 0; k < 32; k++) {
            float a0 = xs[(mg*4 + 0)*32 + k];   // broadcast LDS within warp
            float a1 = xs[(mg*4 + 1)*32 + k];
            float a2 = xs[(mg*4 + 2)*32 + k];
            float a3 = xs[(mg*4 + 3)*32 + k];
            unsigned long long A0, A1, A2, A3;
            PACK2(A0, a0); PACK2(A1, a1); PACK2(A2, a2); PACK2(A3, a3);

            ulonglong2 b01 = *(const ulonglong2*)(ws + k*256 + ng*4);        // LDS.128
            ulonglong2 b23 = *(const ulonglong2*)(ws + k*256 + 128 + ng*4);  // LDS.128

            FFMA2(acc2[0][0], A0, b01.x); FFMA2(acc2[0][1], A0, b01.y);
            FFMA2(acc2[0][2], A0, b23.x); FFMA2(acc2[0][3], A0, b23.y);
            FFMA2(acc2[1][0], A1, b01.x); FFMA2(acc2[1][1], A1, b01.y);
            FFMA2(acc2[1][2], A1, b23.x); FFMA2(acc2[1][3], A1, b23.y);
            FFMA2(acc2[2][0], A2, b01.x); FFMA2(acc2[2][1], A2, b01.y);
            FFMA2(acc2[2][2], A2, b23.x); FFMA2(acc2[2][3], A2, b23.y);
            FFMA2(acc2[3][0], A3, b01.x); FFMA2(acc2[3][1], A3, b01.y);
            FFMA2(acc2[3][2], A3, b23.x); FFMA2(acc2[3][3], A3, b23.y);
        }
        __syncthreads();
    }

    const int d0 = (ng * 4) & 63;
    const float4 asv = *(const float4*)(a + d0);
    const float4 adv = *(const float4*)(a + 64 + d0);
    const float4 gv0 = *(const float4*)(gamma + ng*4);
    const float4 gv1 = *(const float4*)(gamma + 128 + ng*4);
    const float4 bv0 = *(const float4*)(beta  + ng*4);
    const float4 bv1 = *(const float4*)(beta  + 128 + ng*4);

    #pragma unroll
    for (int mi = 0; mi < 4; mi++) {
        const int row = row0 + mg*4 + mi;

        float acc[8];
        UNPACK2(acc[0], acc[1], acc2[mi][0]);
        UNPACK2(acc[2], acc[3], acc2[mi][1]);
        UNPACK2(acc[4], acc[5], acc2[mi][2]);
        UNPACK2(acc[6], acc[7], acc2[mi][3]);

        float s = 0.f;
        #pragma unroll
        for (int j = 0; j < 8; j++) s += acc[j];
        #pragma unroll
        for (int o = 16; o; o >>= 1) s += __shfl_xor_sync(0xffffffffu, s, o);
        const float mu = s * (1.0f / FOUT);

        float q = 0.f;
        #pragma unroll
        for (int j = 0; j < 8; j++) { float dv = acc[j] - mu; q += dv * dv; }
        #pragma unroll
        for (int o = 16; o; o >>= 1) q += __shfl_xor_sync(0xffffffffu, q, o);
        const float rstd = rsqrtf(q * (1.0f / FOUT) + 1e-5f);

        float hn[8];
        hn[0] = (acc[0]-mu)*rstd*gv0.x + bv0.x;
        hn[1] = (acc[1]-mu)*rstd*gv0.y + bv0.y;
        hn[2] = (acc[2]-mu)*rstd*gv0.z + bv0.z;
        hn[3] = (acc[3]-mu)*rstd*gv0.w + bv0.w;
        hn[4] = (acc[4]-mu)*rstd*gv1.x + bv1.x;
        hn[5] = (acc[5]-mu)*rstd*gv1.y + bv1.y;
        hn[6] = (acc[6]-mu)*rstd*gv1.z + bv1.z;
        hn[7] = (acc[7]-mu)*rstd*gv1.w + bv1.w;

        __half2* hp0 = (__half2*)(g_hh + (size_t)row * FOUT + ng*4);
        hp0[0] = __floats2half2_rn(hn[0], hn[1]);
        hp0[1] = __floats2half2_rn(hn[2], hn[3]);
        __half2* hp1 = (__half2*)(g_hh + (size_t)row * FOUT + 128 + ng*4);
        hp1[0] = __floats2half2_rn(hn[4], hn[5]);
        hp1[1] = __floats2half2_rn(hn[6], hn[7]);

        float psl = hn[0]*asv.x + hn[1]*asv.y + hn[2]*asv.z + hn[3]*asv.w;
        float psh = hn[4]*asv.x + hn[5]*asv.y + hn[6]*asv.z + hn[7]*asv.w;
        float pdl = hn[0]*adv.x + hn[1]*adv.y + hn[2]*adv.z + hn[3]*adv.w;
        float pdh = hn[4]*adv.x + hn[5]*adv.y + hn[6]*adv.z + hn[7]*adv.w;
        #pragma unroll
        for (int o = 8; o; o >>= 1) {
            psl += __shfl_xor_sync(0xffffffffu, psl, o);
            psh += __shfl_xor_sync(0xffffffffu, psh, o);
            pdl += __shfl_xor_sync(0xffffffffu, pdl, o);
            pdh += __shfl_xor_sync(0xffffffffu, pdh, o);
        }
        if (ng == 0) {
            g_ei[row*H + 0] = psl; g_ei[row*H + 2] = psh;
            g_ej[row*H + 0] = pdl; g_ej[row*H + 2] = pdh;
        } else if (ng == 16) {
            g_ei[row*H + 1] = psl; g_ei[row*H + 3] = psh;
            g_ej[row*H + 1] = pdl; g_ej[row*H + 3] = pdh;
        }
    }
}

// ---------------------------------------------------------------------------
// Kernel 2: sparse masked-softmax aggregation.
// Gather: 8 neighbors in flight (one per warp slot); each lane loads 8 halves
// (LDG.128); list index is a warp-broadcast LDS. SMEM tree-reduce of 8 partials.
// ---------------------------------------------------------------------------
__global__ __launch_bounds__(256) void agg_kernel(const float* __restrict__ adj,
                                                  float* __restrict__ out) {
    __shared__ unsigned short list[N];
    __shared__ float4 wgt[N];            // exp weights per neighbor (4 heads)
    __shared__ int    warpTot[8];
    __shared__ float  redsum[8*4];
    __shared__ float  Sh[4];
    __shared__ float4 part[8][32][2];    // [slot][lane][half]: 8 KB

    const int row = blockIdx.x;
    const int b   = row >> 10;
    const int t   = threadIdx.x;
    const int warp = t >> 5, lane = t & 31;

    // ---- Phase 1: deterministic compaction of adjacency row ----
    const float* arow = adj + (size_t)row * N;
    float4 av = *(const float4*)(arow + t*4);
    int c = 0;
    unsigned short loc[4];
    if (av.x != 0.f) loc[c++] = (unsigned short)(t*4 + 0);
    if (av.y != 0.f) loc[c++] = (unsigned short)(t*4 + 1);
    if (av.z != 0.f) loc[c++] = (unsigned short)(t*4 + 2);
    if (av.w != 0.f) loc[c++] = (unsigned short)(t*4 + 3);
    int incl = c;
    #pragma unroll
    for (int o = 1; o < 32; o <<= 1) {
        int n = __shfl_up_sync(0xffffffffu, incl, o);
        if (lane >= o) incl += n;
    }
    if (lane == 31) warpTot[warp] = incl;
    __syncthreads();
    int wbase = 0;
    #pragma unroll
    for (int w = 0; w < 8; w++) if (w < warp) wbase += warpTot[w];
    int pos = wbase + incl - c;
    for (int q = 0; q < c; q++) list[pos + q] = loc[q];
    int deg = 0;
    #pragma unroll
    for (int w = 0; w < 8; w++) deg += warpTot[w];
    __syncthreads();

    const float4 ei = *(const float4*)(g_ei + row*H);

    // ---- Phase 2: exp weights + denominators (no max subtraction) ----
    const float* ejbase = g_ej + b*N*H;
    float s0 = 0.f, s1 = 0.f, s2 = 0.f, s3 = 0.f;
    for (int idx = t; idx < deg; idx += 256) {
        int j = list[idx];
        float4 ej = *(const float4*)(ejbase + j*H);
        float v0 = ei.x + ej.x; v0 = v0 > 0.f ? v0 : 0.2f*v0;
        float v1 = ei.y + ej.y; v1 = v1 > 0.f ? v1 : 0.2f*v1;
        float v2 = ei.z + ej.z; v2 = v2 > 0.f ? v2 : 0.2f*v2;
        float v3 = ei.w + ej.w; v3 = v3 > 0.f ? v3 : 0.2f*v3;
        float w0 = __expf(v0), w1 = __expf(v1);
        float w2 = __expf(v2), w3 = __expf(v3);
        wgt[idx] = make_float4(w0, w1, w2, w3);
        s0 += w0; s1 += w1; s2 += w2; s3 += w3;
    }
    #pragma unroll
    for (int o = 16; o; o >>= 1) {
        s0 += __shfl_xor_sync(0xffffffffu, s0, o);
        s1 += __shfl_xor_sync(0xffffffffu, s1, o);
        s2 += __shfl_xor_sync(0xffffffffu, s2, o);
        s3 += __shfl_xor_sync(0xffffffffu, s3, o);
    }
    if (lane == 0) {
        redsum[warp*4+0] = s0; redsum[warp*4+1] = s1;
        redsum[warp*4+2] = s2; redsum[warp*4+3] = s3;
    }
    __syncthreads();
    if (t < 4) {
        float ss = 0.f;
        #pragma unroll
        for (int w = 0; w < 8; w++) ss += redsum[w*4 + t];
        Sh[t] = ss;
    }
    __syncthreads();

    // ---- Phase 3: wide gather. slot = warp (8 neighbors in flight),
    //      lane owns features [lane*8, lane*8+8) -> one LDG.128 per neighbor.
    const int head = lane >> 3;                 // (lane*8)>>6
    const __half* hbase = g_hh + b * (N*FOUT);
    const float*  wf    = (const float*)wgt;

    float a0=0.f,a1=0.f,a2=0.f,a3=0.f,a4=0.f,a5=0.f,a6=0.f,a7=0.f;
    for (int idx = warp; idx < deg; idx += 8) {
        int j = (int)list[idx];                 // warp-broadcast LDS
        float w = wf[idx*4 + head];
        uint4 raw = *(const uint4*)(hbase + (j << 8) + lane*8);
        float2 u0 = __half22float2(*(const __half2*)&raw.x);
        float2 u1 = __half22float2(*(const __half2*)&raw.y);
        float2 u2 = __half22float2(*(const __half2*)&raw.z);
        float2 u3 = __half22float2(*(const __half2*)&raw.w);
        a0 += w*u0.x; a1 += w*u0.y; a2 += w*u1.x; a3 += w*u1.y;
        a4 += w*u2.x; a5 += w*u2.y; a6 += w*u3.x; a7 += w*u3.y;
    }
    part[warp][lane][0] = make_float4(a0, a1, a2, a3);
    part[warp][lane][1] = make_float4(a4, a5, a6, a7);
    __syncthreads();

    if (t < 64) {   // u = t: lane32 = t&31 picks feature octet, hs = t>>5 picks quad
        const int lane32 = t & 31;
        const int hs     = t >> 5;
        float4 r = part[0][lane32][hs];
        #pragma unroll
        for (int s = 1; s < 8; s++) {
            float4 p = part[s][lane32][hs];
            r.x += p.x; r.y += p.y; r.z += p.z; r.w += p.w;
        }
        const float inv = 1.0f / Sh[lane32 >> 3];
        r.x *= inv; r.y *= inv; r.z *= inv; r.w *= inv;
        *(float4*)(out + (size_t)row * FOUT + lane32*8 + hs*4) = r;
    }
}

// ---------------------------------------------------------------------------
extern "C" void kernel_launch(void* const* d_in, const int* in_sizes, int n_in,
                              void* d_out, int out_size) {
    const float* x     = (const float*)d_in[0];
    const float* adj   = (const float*)d_in[1];
    const float* W     = (const float*)d_in[2];
    const float* gamma = (const float*)d_in[3];
    const float* beta  = (const float*)d_in[4];
    const float* a     = (const float*)d_in[5];
    float* out = (float*)d_out;

    gemm_ln_kernel<<<BN/32, 256>>>(x, W, gamma, beta, a);
    agg_kernel    <<<BN,    256>>>(adj, out);
}

// round 8
// speedup vs baseline: 1.9579x; 1.2501x over previous
#include <cuda_runtime.h>
#include <cuda_fp16.h>
#include <mma.h>

using namespace nvcuda;

#define B 8
#define N 1024
#define FIN 256
#define FOUT 256
#define H 4
#define D 64
#define BN (B*N)

// Scratch (static __device__ — no allocation allowed)
__device__ __half g_hh[BN*FOUT];   // fp16 normalized features (gather source)
__device__ float  g_ei[BN*H];
__device__ float  g_ej[BN*H];

// SMEM layout for the GEMM kernel (bytes):
//   Ahi: 32x40 half  = 2560      @ 0
//   Alo: 32x40 half  = 2560      @ 2560
//   Bhi: 32x264 half = 16896     @ 5120
//   Blo: 32x264 half = 16896     @ 22016
//   total staging              = 38912
//   epilogue out: 32x256 float = 32768 (aliases staging after mainloop)
#define LDA 40
#define LDB 264

// ---------------------------------------------------------------------------
// Kernel 1: h = x @ W via split-fp16 tensor-core MMA (fp32-class precision),
// fused LayerNorm + head logits epilogue.
// Block tile 32 rows x 256 cols, 256 threads (8 warps, warp tile 16x64).
// ---------------------------------------------------------------------------
__global__ __launch_bounds__(256) void gemm_ln_kernel(const float* __restrict__ x,
                                                      const float* __restrict__ W,
                                                      const float* __restrict__ gamma,
                                                      const float* __restrict__ beta,
                                                      const float* __restrict__ a) {
    __shared__ __align__(32) char smem_raw[38912];
    __half* Ahi = (__half*)smem_raw;
    __half* Alo = Ahi + 32*LDA;
    __half* Bhi = (__half*)(smem_raw + 5120);
    __half* Blo = Bhi + 32*LDB;
    float*  outS = (float*)smem_raw;     // epilogue alias

    const int tid  = threadIdx.x;
    const int row0 = blockIdx.x * 32;
    const int wid  = tid >> 5, lane = tid & 31;
    const int wr   = wid >> 2;           // 0..1: warp row  (16 rows)
    const int wc   = wid & 3;            // 0..3: warp col  (64 cols)

    wmma::fragment<wmma::accumulator, 16, 16, 16, float> acc[4];
    #pragma unroll
    for (int c = 0; c < 4; c++) wmma::fill_fragment(acc[c], 0.0f);

    for (int kk = 0; kk < FIN; kk += 32) {
        // ---- stage x tile (32 rows x 32 k), split hi/lo ----
        {
            int r  = tid >> 3;
            int k4 = (tid & 7) * 4;
            float4 v = *(const float4*)(x + (size_t)(row0 + r) * FIN + kk + k4);
            float vv[4] = {v.x, v.y, v.z, v.w};
            #pragma unroll
            for (int i = 0; i < 4; i++) {
                __half hi = __float2half_rn(vv[i]);
                Ahi[r*LDA + k4 + i] = hi;
                Alo[r*LDA + k4 + i] = __float2half_rn(vv[i] - __half2float(hi));
            }
        }
        // ---- stage W tile (32 k x 256 n), split hi/lo ----
        #pragma unroll
        for (int i = 0; i < 8; i++) {
            int w  = tid + i * 256;       // float4 index
            int k  = w >> 6;
            int c4 = (w & 63) * 4;
            float4 v = *(const float4*)(W + (size_t)(kk + k) * FOUT + c4);
            float vv[4] = {v.x, v.y, v.z, v.w};
            #pragma unroll
            for (int j = 0; j < 4; j++) {
                __half hi = __float2half_rn(vv[j]);
                Bhi[k*LDB + c4 + j] = hi;
                Blo[k*LDB + c4 + j] = __float2half_rn(vv[j] - __half2float(hi));
            }
        }
        __syncthreads();

        #pragma unroll
        for (int ks = 0; ks < 2; ks++) {
            wmma::fragment<wmma::matrix_a, 16, 16, 16, __half, wmma::row_major> ahi, alo;
            wmma::load_matrix_sync(ahi, Ahi + (wr*16)*LDA + ks*16, LDA);
            wmma::load_matrix_sync(alo, Alo + (wr*16)*LDA + ks*16, LDA);
            #pragma unroll
            for (int c = 0; c < 4; c++) {
                wmma::fragment<wmma::matrix_b, 16, 16, 16, __half, wmma::row_major> bhi, blo;
                wmma::load_matrix_sync(bhi, Bhi + (ks*16)*LDB + wc*64 + c*16, LDB);
                wmma::load_matrix_sync(blo, Blo + (ks*16)*LDB + wc*64 + c*16, LDB);
                wmma::mma_sync(acc[c], ahi, bhi, acc[c]);
                wmma::mma_sync(acc[c], ahi, blo, acc[c]);
                wmma::mma_sync(acc[c], alo, bhi, acc[c]);
            }
        }
        __syncthreads();
    }

    // ---- epilogue: accum tile -> SMEM, then LN + logits ----
    #pragma unroll
    for (int c = 0; c < 4; c++)
        wmma::store_matrix_sync(outS + (wr*16)*256 + wc*64 + c*16, acc[c], 256,
                                wmma::mem_row_major);
    __syncthreads();

    // warp wid owns rows wid*4 .. wid*4+3; lane owns features [lane*8, lane*8+8)
    const int f0   = lane * 8;
    const int d0   = f0 & 63;
    const int head = lane >> 3;
    const float4 as0 = *(const float4*)(a + d0);
    const float4 as1 = *(const float4*)(a + d0 + 4);
    const float4 ad0 = *(const float4*)(a + 64 + d0);
    const float4 ad1 = *(const float4*)(a + 64 + d0 + 4);
    const float4 gv0 = *(const float4*)(gamma + f0);
    const float4 gv1 = *(const float4*)(gamma + f0 + 4);
    const float4 bv0 = *(const float4*)(beta + f0);
    const float4 bv1 = *(const float4*)(beta + f0 + 4);

    #pragma unroll
    for (int r = 0; r < 4; r++) {
        const int rloc = wid*4 + r;
        const int row  = row0 + rloc;
        float4 h0 = *(const float4*)(outS + rloc*256 + f0);
        float4 h1 = *(const float4*)(outS + rloc*256 + f0 + 4);
        float hv[8] = {h0.x,h0.y,h0.z,h0.w,h1.x,h1.y,h1.z,h1.w};

        float s = 0.f;
        #pragma unroll
        for (int j = 0; j < 8; j++) s += hv[j];
        #pragma unroll
        for (int o = 16; o; o >>= 1) s += __shfl_xor_sync(0xffffffffu, s, o);
        const float mu = s * (1.0f / FOUT);

        float q = 0.f;
        #pragma unroll
        for (int j = 0; j < 8; j++) { float dv = hv[j] - mu; q += dv*dv; }
        #pragma unroll
        for (int o = 16; o; o >>= 1) q += __shfl_xor_sync(0xffffffffu, q, o);
        const float rstd = rsqrtf(q * (1.0f / FOUT) + 1e-5f);

        float hn[8];
        hn[0] = (hv[0]-mu)*rstd*gv0.x + bv0.x;
        hn[1] = (hv[1]-mu)*rstd*gv0.y + bv0.y;
        hn[2] = (hv[2]-mu)*rstd*gv0.z + bv0.z;
        hn[3] = (hv[3]-mu)*rstd*gv0.w + bv0.w;
        hn[4] = (hv[4]-mu)*rstd*gv1.x + bv1.x;
        hn[5] = (hv[5]-mu)*rstd*gv1.y + bv1.y;
        hn[6] = (hv[6]-mu)*rstd*gv1.z + bv1.z;
        hn[7] = (hv[7]-mu)*rstd*gv1.w + bv1.w;

        // fp16 mirror store (one STG.128)
        __half2 p0 = __floats2half2_rn(hn[0], hn[1]);
        __half2 p1 = __floats2half2_rn(hn[2], hn[3]);
        __half2 p2 = __floats2half2_rn(hn[4], hn[5]);
        __half2 p3 = __floats2half2_rn(hn[6], hn[7]);
        uint4 packed;
        packed.x = *(unsigned int*)&p0; packed.y = *(unsigned int*)&p1;
        packed.z = *(unsigned int*)&p2; packed.w = *(unsigned int*)&p3;
        *(uint4*)(g_hh + (size_t)row * FOUT + f0) = packed;

        // head logits: reduce over the 8-lane group covering this head
        float ps = hn[0]*as0.x + hn[1]*as0.y + hn[2]*as0.z + hn[3]*as0.w
                 + hn[4]*as1.x + hn[5]*as1.y + hn[6]*as1.z + hn[7]*as1.w;
        float pd = hn[0]*ad0.x + hn[1]*ad0.y + hn[2]*ad0.z + hn[3]*ad0.w
                 + hn[4]*ad1.x + hn[5]*ad1.y + hn[6]*ad1.z + hn[7]*ad1.w;
        #pragma unroll
        for (int o = 4; o; o >>= 1) {
            ps += __shfl_xor_sync(0xffffffffu, ps, o);
            pd += __shfl_xor_sync(0xffffffffu, pd, o);
        }
        if ((lane & 7) == 0) {
            g_ei[row*H + head] = ps;
            g_ej[row*H + head] = pd;
        }
    }
}

// ---------------------------------------------------------------------------
// Kernel 2: sparse masked-softmax aggregation (unchanged from R7).
// ---------------------------------------------------------------------------
__global__ __launch_bounds__(256) void agg_kernel(const float* __restrict__ adj,
                                                  float* __restrict__ out) {
    __shared__ unsigned short list[N];
    __shared__ float4 wgt[N];
    __shared__ int    warpTot[8];
    __shared__ float  redsum[8*4];
    __shared__ float  Sh[4];
    __shared__ float4 part[8][32][2];

    const int row = blockIdx.x;
    const int b   = row >> 10;
    const int t   = threadIdx.x;
    const int warp = t >> 5, lane = t & 31;

    // ---- Phase 1: deterministic compaction of adjacency row ----
    const float* arow = adj + (size_t)row * N;
    float4 av = *(const float4*)(arow + t*4);
    int c = 0;
    unsigned short loc[4];
    if (av.x != 0.f) loc[c++] = (unsigned short)(t*4 + 0);
    if (av.y != 0.f) loc[c++] = (unsigned short)(t*4 + 1);
    if (av.z != 0.f) loc[c++] = (unsigned short)(t*4 + 2);
    if (av.w != 0.f) loc[c++] = (unsigned short)(t*4 + 3);
    int incl = c;
    #pragma unroll
    for (int o = 1; o < 32; o <<= 1) {
        int n = __shfl_up_sync(0xffffffffu, incl, o);
        if (lane >= o) incl += n;
    }
    if (lane == 31) warpTot[warp] = incl;
    __syncthreads();
    int wbase = 0;
    #pragma unroll
    for (int w = 0; w < 8; w++) if (w < warp) wbase += warpTot[w];
    int pos = wbase + incl - c;
    for (int q = 0; q < c; q++) list[pos + q] = loc[q];
    int deg = 0;
    #pragma unroll
    for (int w = 0; w < 8; w++) deg += warpTot[w];
    __syncthreads();

    const float4 ei = *(const float4*)(g_ei + row*H);

    // ---- Phase 2: exp weights + denominators (no max subtraction) ----
    const float* ejbase = g_ej + b*N*H;
    float s0 = 0.f, s1 = 0.f, s2 = 0.f, s3 = 0.f;
    for (int idx = t; idx < deg; idx += 256) {
        int j = list[idx];
        float4 ej = *(const float4*)(ejbase + j*H);
        float v0 = ei.x + ej.x; v0 = v0 > 0.f ? v0 : 0.2f*v0;
        float v1 = ei.y + ej.y; v1 = v1 > 0.f ? v1 : 0.2f*v1;
        float v2 = ei.z + ej.z; v2 = v2 > 0.f ? v2 : 0.2f*v2;
        float v3 = ei.w + ej.w; v3 = v3 > 0.f ? v3 : 0.2f*v3;
        float w0 = __expf(v0), w1 = __expf(v1);
        float w2 = __expf(v2), w3 = __expf(v3);
        wgt[idx] = make_float4(w0, w1, w2, w3);
        s0 += w0; s1 += w1; s2 += w2; s3 += w3;
    }
    #pragma unroll
    for (int o = 16; o; o >>= 1) {
        s0 += __shfl_xor_sync(0xffffffffu, s0, o);
        s1 += __shfl_xor_sync(0xffffffffu, s1, o);
        s2 += __shfl_xor_sync(0xffffffffu, s2, o);
        s3 += __shfl_xor_sync(0xffffffffu, s3, o);
    }
    if (lane == 0) {
        redsum[warp*4+0] = s0; redsum[warp*4+1] = s1;
        redsum[warp*4+2] = s2; redsum[warp*4+3] = s3;
    }
    __syncthreads();
    if (t < 4) {
        float ss = 0.f;
        #pragma unroll
        for (int w = 0; w < 8; w++) ss += redsum[w*4 + t];
        Sh[t] = ss;
    }
    __syncthreads();

    // ---- Phase 3: wide gather (8 neighbors in flight, LDG.128/lane) ----
    const int head = lane >> 3;
    const __half* hbase = g_hh + b * (N*FOUT);
    const float*  wf    = (const float*)wgt;

    float a0=0.f,a1=0.f,a2=0.f,a3=0.f,a4=0.f,a5=0.f,a6=0.f,a7=0.f;
    for (int idx = warp; idx < deg; idx += 8) {
        int j = (int)list[idx];
        float w = wf[idx*4 + head];
        uint4 raw = *(const uint4*)(hbase + (j << 8) + lane*8);
        float2 u0 = __half22float2(*(const __half2*)&raw.x);
        float2 u1 = __half22float2(*(const __half2*)&raw.y);
        float2 u2 = __half22float2(*(const __half2*)&raw.z);
        float2 u3 = __half22float2(*(const __half2*)&raw.w);
        a0 += w*u0.x; a1 += w*u0.y; a2 += w*u1.x; a3 += w*u1.y;
        a4 += w*u2.x; a5 += w*u2.y; a6 += w*u3.x; a7 += w*u3.y;
    }
    part[warp][lane][0] = make_float4(a0, a1, a2, a3);
    part[warp][lane][1] = make_float4(a4, a5, a6, a7);
    __syncthreads();

    if (t < 64) {
        const int lane32 = t & 31;
        const int hs     = t >> 5;
        float4 r = part[0][lane32][hs];
        #pragma unroll
        for (int s = 1; s < 8; s++) {
            float4 p = part[s][lane32][hs];
            r.x += p.x; r.y += p.y; r.z += p.z; r.w += p.w;
        }
        const float inv = 1.0f / Sh[lane32 >> 3];
        r.x *= inv; r.y *= inv; r.z *= inv; r.w *= inv;
        *(float4*)(out + (size_t)row * FOUT + lane32*8 + hs*4) = r;
    }
}

// ---------------------------------------------------------------------------
extern "C" void kernel_launch(void* const* d_in, const int* in_sizes, int n_in,
                              void* d_out, int out_size) {
    const float* x     = (const float*)d_in[0];
    const float* adj   = (const float*)d_in[1];
    const float* W     = (const float*)d_in[2];
    const float* gamma = (const float*)d_in[3];
    const float* beta  = (const float*)d_in[4];
    const float* a     = (const float*)d_in[5];
    float* out = (float*)d_out;

    gemm_ln_kernel<<<BN/32, 256>>>(x, W, gamma, beta, a);
    agg_kernel    <<<BN,    256>>>(adj, out);
}